// round 16
// baseline (speedup 1.0000x reference)
#include <cuda_runtime.h>
#include <cuda_fp16.h>
#include <cstdint>

// Problem constants
#define MAXN 100000
#define MAXE 200000

// -------- scratch (static device globals; no allocation) --------
// w_e stored fp16, TRANSPOSED per edge: g_weh[e][o][i] at flat col n = o*32+i
__device__ __half g_weh[(size_t)MAXE * 1024];   // 409.6 MB
__device__ __half g_w2h[1024 * 128];            // fp16 W2, rows PERMUTED by sr(n)
__device__ float g_b2p[1024];                   // permuted b2
__device__ float g_out[MAXN * 32];
__device__ float g_agg[MAXN * 32];
__device__ float g_cnt[MAXN];

__device__ __forceinline__ uint32_t smem_u32(const void* p) {
    uint32_t a;
    asm("{ .reg .u64 t; cvta.to.shared.u64 t, %1; cvt.u32.u64 %0, t; }" : "=r"(a) : "l"(p));
    return a;
}
__device__ __forceinline__ void ldsm_x4(uint32_t& r0, uint32_t& r1, uint32_t& r2, uint32_t& r3,
                                        uint32_t addr) {
    asm volatile("ldmatrix.sync.aligned.m8n8.x4.shared.b16 {%0,%1,%2,%3}, [%4];"
        : "=r"(r0), "=r"(r1), "=r"(r2), "=r"(r3) : "r"(addr));
}
__device__ __forceinline__ void mma16816(float* d, const uint32_t* a, const uint32_t* b) {
    asm volatile("mma.sync.aligned.m16n8k16.row.col.f32.f16.f16.f32 "
        "{%0,%1,%2,%3}, {%4,%5,%6,%7}, {%8,%9}, {%0,%1,%2,%3};"
        : "+f"(d[0]), "+f"(d[1]), "+f"(d[2]), "+f"(d[3])
        : "r"(a[0]), "r"(a[1]), "r"(a[2]), "r"(a[3]), "r"(b[0]), "r"(b[1]));
}
#define CP_ASYNC16(dst, src) \
    asm volatile("cp.async.cg.shared.global [%0], [%1], 16;" :: "r"(dst), "l"(src))
#define CP_COMMIT() asm volatile("cp.async.commit_group;")
#define CP_WAIT0()  asm volatile("cp.async.wait_group 0;")

// ============================================================
// prep: W2 fp32 [1024,128] -> fp16, rows permuted by sr(n); also permuted b2
// ============================================================
__global__ void k_prep(const float* __restrict__ w2, const float* __restrict__ b2) {
    int i = blockIdx.x * blockDim.x + threadIdx.x;
    if (i >= 1024 * 128) return;
    int n = i >> 7, k = i & 127;
    int sr = ((n & 31) << 5) | (n >> 5);
    g_w2h[n * 128 + k] = __float2half(w2[(size_t)sr * 128 + k]);
    if (k == 0) g_b2p[n] = b2[sr];
}

// ============================================================
// count / lin0 (lin0 fuses the agg+cnt zeroing)
// ============================================================
__global__ void k_count(const int* __restrict__ dst, int e) {
    int t = blockIdx.x * blockDim.x + threadIdx.x;
    if (t < e) atomicAdd(&g_cnt[dst[t]], 1.f);
}
__global__ void k_lin0(const float* __restrict__ x, const float* __restrict__ w,
                       const float* __restrict__ b, int n) {
    __shared__ float wT[16 * 32];
    __shared__ float bs[32];
    int t = threadIdx.x;
    for (int i = t; i < 512; i += blockDim.x) {
        int d = i >> 4, k = i & 15;
        wT[k * 32 + d] = w[i];
    }
    if (t < 32) bs[t] = b[t];
    __syncthreads();
    int warp = (blockIdx.x * blockDim.x + t) >> 5;
    int lane = t & 31;
    if (warp >= n) return;
    float xk = (lane < 16) ? x[(size_t)warp * 16 + lane] : 0.f;
    float acc = bs[lane];
#pragma unroll
    for (int k = 0; k < 16; k++) {
        float xv = __shfl_sync(0xffffffffu, xk, k);
        acc = fmaf(wT[k * 32 + lane], xv, acc);
    }
    size_t base = (size_t)warp * 32 + lane;
    g_out[base] = fmaxf(acc, 0.f);
    g_agg[base] = 0.f;          // fused init
    if (lane == 0) g_cnt[warp] = 0.f;
}

// ============================================================
// w_e GEMM via mma.sync: one CTA = 128 edges x FULL 1024 cols, K=128.
// ============================================================
#define STR_H 136
#define BUF_HALVES (128 * STR_H)
#define WE_SMEM_BYTES (3 * BUF_HALVES * 2)   // A + 2 B buffers

__global__ __launch_bounds__(256, 2) void k_we(
    const float* __restrict__ ea, const float* __restrict__ w1,
    const float* __restrict__ b1, int E)
{
    extern __shared__ __half smh[];
    __half* Asm = smh;                    // [128 el][136 k]
    __half* Bsm[2] = { smh + BUF_HALVES, smh + 2 * BUF_HALVES };
    __shared__ float eas[128 * 5];
    __shared__ float w1s[128 * 5];
    __shared__ float b1s[128];

    const int tid = threadIdx.x;
    const int w = tid >> 5;
    const int lane = tid & 31;
    const int ebase = blockIdx.x * 128;

#define STAGE_B(chunk, buf) do { \
        const __half* gsrc = g_w2h + (size_t)(chunk) * 128 * 128; \
        for (int i = tid; i < 2048; i += 256) { \
            int n = i >> 4, k0 = (i & 15) * 8; \
            uint32_t dsa = smem_u32(&Bsm[buf][n * STR_H + k0]); \
            CP_ASYNC16(dsa, gsrc + n * 128 + k0); \
        } \
        CP_COMMIT(); \
    } while (0)

    STAGE_B(0, 0);

    for (int i = tid; i < 640; i += 256) {
        int el = i / 5, j = i - el * 5;
        int ge = ebase + el;
        eas[i] = (ge < E) ? ea[(size_t)ge * 5 + j] : 0.f;
        w1s[i] = __ldg(&w1[i]);
    }
    if (tid < 128) b1s[tid] = __ldg(&b1[tid]);
    __syncthreads();

    for (int i = tid; i < 16384; i += 256) {
        int el = i >> 7, h = i & 127;
        float a = b1s[h];
        const float* e5 = &eas[el * 5];
        const float* w5 = &w1s[h * 5];
#pragma unroll
        for (int j = 0; j < 5; j++)
            a = fmaf(e5[j], w5[j], a);
        Asm[el * STR_H + h] = __float2half(fmaxf(a, 0.f));
    }
    CP_WAIT0();
    __syncthreads();

    const uint32_t Abase = smem_u32(Asm);
    const int R = (w & 3) * 32;
    const int C = (w >> 2) * 64;
    const int lt = lane >> 3;
    const int lr = lane & 7;
    const int qr = lane >> 2, qc = (lane & 3) * 2;

    for (int chunk = 0; chunk < 8; chunk++) {
        const int cur = chunk & 1;
        const uint32_t Bbase = smem_u32(Bsm[cur]);
        if (chunk < 7) STAGE_B(chunk + 1, cur ^ 1);

        float acc[2][8][4];
#pragma unroll
        for (int rt = 0; rt < 2; rt++)
#pragma unroll
            for (int nt = 0; nt < 8; nt++)
#pragma unroll
                for (int q = 0; q < 4; q++) acc[rt][nt][q] = 0.f;

#pragma unroll
        for (int ks = 0; ks < 8; ks++) {
            uint32_t a[2][4];
#pragma unroll
            for (int rt = 0; rt < 2; rt++) {
                int row = R + rt * 16 + (lt & 1) * 8 + lr;
                int kseg = lt >> 1;
                ldsm_x4(a[rt][0], a[rt][1], a[rt][2], a[rt][3],
                        Abase + (row * STR_H + ks * 16 + kseg * 8) * 2);
            }
            uint32_t b[8][2];
#pragma unroll
            for (int np = 0; np < 4; np++) {
                int n = C + np * 16 + (lt >> 1) * 8 + lr;
                int kseg = lt & 1;
                uint32_t r0, r1, r2, r3;
                ldsm_x4(r0, r1, r2, r3, Bbase + (n * STR_H + ks * 16 + kseg * 8) * 2);
                b[2 * np][0] = r0; b[2 * np][1] = r1;
                b[2 * np + 1][0] = r2; b[2 * np + 1][1] = r3;
            }
#pragma unroll
            for (int rt = 0; rt < 2; rt++)
#pragma unroll
                for (int nt = 0; nt < 8; nt++)
                    mma16816(acc[rt][nt], a[rt], b[nt]);
        }

        __syncthreads();
        {
            __half* Esm = Bsm[cur];
            const int colbase = chunk * 128;
#pragma unroll
            for (int rt = 0; rt < 2; rt++) {
#pragma unroll
                for (int h8 = 0; h8 < 2; h8++) {
                    int row = R + rt * 16 + h8 * 8 + qr;
#pragma unroll
                    for (int nt = 0; nt < 8; nt++) {
                        int c = C + nt * 8 + qc;
                        float d0 = acc[rt][nt][h8 * 2 + 0] + __ldg(&g_b2p[colbase + c]);
                        float d1 = acc[rt][nt][h8 * 2 + 1] + __ldg(&g_b2p[colbase + c + 1]);
                        *(__half2*)&Esm[row * STR_H + c] = __floats2half2_rn(d0, d1);
                    }
                }
            }
            __syncthreads();
            for (int i = tid; i < 2048; i += 256) {
                int row = i >> 4, seg = i & 15;
                int ge = ebase + row;
                if (ge < E)
                    *(uint4*)(g_weh + (size_t)ge * 1024 + colbase + seg * 8) =
                        *(const uint4*)&Esm[row * STR_H + seg * 8];
            }
        }
        if (chunk < 7) {
            CP_WAIT0();
            __syncthreads();
        }
    }
#undef STAGE_B
}

// ============================================================
// message pass: TWO edges per warp (8 independent LDG.128 per
// thread in flight) -> double memory-level parallelism.
// ============================================================
__global__ void k_msg(const int* __restrict__ src, const int* __restrict__ dst, int e) {
    int w = (blockIdx.x * blockDim.x + threadIdx.x) >> 5;
    int lane = threadIdx.x & 31;
    int e0 = 2 * w, e1 = 2 * w + 1;
    if (e0 >= e) return;
    bool has1 = (e1 < e);

    int s0 = __ldg(&src[e0]);
    int d0 = __ldg(&dst[e0]);
    int s1 = has1 ? __ldg(&src[e1]) : s0;
    int d1 = has1 ? __ldg(&dst[e1]) : d0;

    const uint4* wp0 = (const uint4*)(g_weh + (size_t)e0 * 1024 + lane * 32);
    const uint4* wp1 = (const uint4*)(g_weh + (size_t)(has1 ? e1 : e0) * 1024 + lane * 32);
    // issue all 8 loads before consuming any
    uint4 a0 = __ldcs(&wp0[0]);
    uint4 a1 = __ldcs(&wp0[1]);
    uint4 a2 = __ldcs(&wp0[2]);
    uint4 a3 = __ldcs(&wp0[3]);
    uint4 b0 = __ldcs(&wp1[0]);
    uint4 b1 = __ldcs(&wp1[1]);
    uint4 b2 = __ldcs(&wp1[2]);
    uint4 b3 = __ldcs(&wp1[3]);
    float sv0 = __ldg(&g_out[(size_t)s0 * 32 + lane]);
    float sv1 = __ldg(&g_out[(size_t)s1 * 32 + lane]);

    float acc0 = 0.f, acc1 = 0.f;
#define ACC2(ACC, SV, u, i0) do { \
        float2 f_ = __half22float2(*(const __half2*)&(u)); \
        ACC = fmaf(__shfl_sync(0xffffffffu, SV, (i0)), f_.x, ACC); \
        ACC = fmaf(__shfl_sync(0xffffffffu, SV, (i0) + 1), f_.y, ACC); \
    } while (0)
    ACC2(acc0, sv0, a0.x, 0);  ACC2(acc0, sv0, a0.y, 2);  ACC2(acc0, sv0, a0.z, 4);  ACC2(acc0, sv0, a0.w, 6);
    ACC2(acc0, sv0, a1.x, 8);  ACC2(acc0, sv0, a1.y, 10); ACC2(acc0, sv0, a1.z, 12); ACC2(acc0, sv0, a1.w, 14);
    ACC2(acc0, sv0, a2.x, 16); ACC2(acc0, sv0, a2.y, 18); ACC2(acc0, sv0, a2.z, 20); ACC2(acc0, sv0, a2.w, 22);
    ACC2(acc0, sv0, a3.x, 24); ACC2(acc0, sv0, a3.y, 26); ACC2(acc0, sv0, a3.z, 28); ACC2(acc0, sv0, a3.w, 30);
    ACC2(acc1, sv1, b0.x, 0);  ACC2(acc1, sv1, b0.y, 2);  ACC2(acc1, sv1, b0.z, 4);  ACC2(acc1, sv1, b0.w, 6);
    ACC2(acc1, sv1, b1.x, 8);  ACC2(acc1, sv1, b1.y, 10); ACC2(acc1, sv1, b1.z, 12); ACC2(acc1, sv1, b1.w, 14);
    ACC2(acc1, sv1, b2.x, 16); ACC2(acc1, sv1, b2.y, 18); ACC2(acc1, sv1, b2.z, 20); ACC2(acc1, sv1, b2.w, 22);
    ACC2(acc1, sv1, b3.x, 24); ACC2(acc1, sv1, b3.y, 26); ACC2(acc1, sv1, b3.z, 28); ACC2(acc1, sv1, b3.w, 30);
#undef ACC2

    atomicAdd(&g_agg[(size_t)d0 * 32 + lane], acc0);
    if (has1) atomicAdd(&g_agg[(size_t)d1 * 32 + lane], acc1);
}

// ============================================================
// fused NNConv-root + GRU update (1024-thread blocks)
// ============================================================
__global__ void k_update(const float* __restrict__ root_w, const float* __restrict__ conv_b,
                         const float* __restrict__ wih, const float* __restrict__ whh,
                         const float* __restrict__ bih, const float* __restrict__ bhh, int n) {
    __shared__ float rootT[32 * 33];
    __shared__ float wihT[32 * 97];
    __shared__ float whhT[32 * 97];
    __shared__ float cb[32], bi[96], bh[96];
    int t = threadIdx.x;
    for (int i = t; i < 1024; i += blockDim.x) {
        int d = i >> 5, j = i & 31;
        rootT[j * 33 + d] = root_w[i];
    }
    for (int i = t; i < 3072; i += blockDim.x) {
        int rr = i >> 5, j = i & 31;
        wihT[j * 97 + rr] = wih[i];
        whhT[j * 97 + rr] = whh[i];
    }
    if (t < 32) cb[t] = conv_b[t];
    if (t < 96) { bi[t] = bih[t]; bh[t] = bhh[t]; }
    __syncthreads();

    int warp = (blockIdx.x * blockDim.x + t) >> 5;
    int lane = t & 31;
    if (warp >= n) return;
    size_t base = (size_t)warp * 32 + lane;

    float h = g_out[base];
    float c = fmaxf(g_cnt[warp], 1.f);
    float m = g_agg[base] / c + cb[lane];
#pragma unroll
    for (int j = 0; j < 32; j++) {
        float hj = __shfl_sync(0xffffffffu, h, j);
        m = fmaf(rootT[j * 33 + lane], hj, m);
    }
    m = fmaxf(m, 0.f);

    float gr = bi[lane], gz = bi[32 + lane], gn = bi[64 + lane];
    float hr = bh[lane], hz = bh[32 + lane], hn = bh[64 + lane];
#pragma unroll
    for (int j = 0; j < 32; j++) {
        float mj = __shfl_sync(0xffffffffu, m, j);
        float hj = __shfl_sync(0xffffffffu, h, j);
        gr = fmaf(wihT[j * 97 + lane], mj, gr);
        gz = fmaf(wihT[j * 97 + 32 + lane], mj, gz);
        gn = fmaf(wihT[j * 97 + 64 + lane], mj, gn);
        hr = fmaf(whhT[j * 97 + lane], hj, hr);
        hz = fmaf(whhT[j * 97 + 32 + lane], hj, hz);
        hn = fmaf(whhT[j * 97 + 64 + lane], hj, hn);
    }
    float r = 1.f / (1.f + __expf(-(gr + hr)));
    float z = 1.f / (1.f + __expf(-(gz + hz)));
    float nn = tanhf(gn + r * hn);
    float hnew = (1.f - z) * nn + z * h;

    g_out[base] = hnew;
    g_agg[base] = 0.f;
}

// ============================================================
// final readout
// ============================================================
__global__ void k_final(const float* __restrict__ l1w, const float* __restrict__ l1b,
                        const float* __restrict__ l2w, const float* __restrict__ l2b,
                        float* __restrict__ out, int n) {
    __shared__ float w1T[32 * 33];
    __shared__ float b1s[32], w2s[32];
    int t = threadIdx.x;
    for (int i = t; i < 1024; i += blockDim.x) {
        int d = i >> 5, j = i & 31;
        w1T[j * 33 + d] = l1w[i];
    }
    if (t < 32) { b1s[t] = l1b[t]; w2s[t] = l2w[t]; }
    __syncthreads();

    int warp = (blockIdx.x * blockDim.x + t) >> 5;
    int lane = t & 31;
    if (warp >= n) return;
    float h = g_out[(size_t)warp * 32 + lane];
    float acc = b1s[lane];
#pragma unroll
    for (int j = 0; j < 32; j++) {
        float hj = __shfl_sync(0xffffffffu, h, j);
        acc = fmaf(w1T[j * 33 + lane], hj, acc);
    }
    acc = fmaxf(acc, 0.f);
    float p = acc * w2s[lane];
#pragma unroll
    for (int off = 16; off; off >>= 1) p += __shfl_xor_sync(0xffffffffu, p, off);
    if (lane == 0) out[warp] = p + __ldg(&l2b[0]);
}

// ============================================================
// launcher — k_msg is the 4th launch so the ncu sampler
// (empirically: 4th kernel) profiles it this round.
// ============================================================
extern "C" void kernel_launch(void* const* d_in, const int* in_sizes, int n_in,
                              void* d_out, int out_size) {
    const float* x      = (const float*)d_in[0];
    const int*   ei     = (const int*)  d_in[1];
    const float* ea     = (const float*)d_in[2];
    const float* lin0_w = (const float*)d_in[3];
    const float* lin0_b = (const float*)d_in[4];
    const float* mlp_w1 = (const float*)d_in[5];
    const float* mlp_b1 = (const float*)d_in[6];
    const float* mlp_w2 = (const float*)d_in[7];
    const float* mlp_b2 = (const float*)d_in[8];
    const float* root_w = (const float*)d_in[9];
    const float* conv_b = (const float*)d_in[10];
    const float* gw_ih  = (const float*)d_in[11];
    const float* gw_hh  = (const float*)d_in[12];
    const float* gb_ih  = (const float*)d_in[13];
    const float* gb_hh  = (const float*)d_in[14];
    const float* lin1_w = (const float*)d_in[15];
    const float* lin1_b = (const float*)d_in[16];
    const float* lin2_w = (const float*)d_in[17];
    const float* lin2_b = (const float*)d_in[18];

    const int n = in_sizes[0] / 16;   // 100000
    const int e = in_sizes[2] / 5;    // 200000
    const int* src = ei;
    const int* dst = ei + e;
    const int msg_grid = (((e + 1) / 2) * 32 + 255) / 256;

    cudaFuncSetAttribute(k_we, cudaFuncAttributeMaxDynamicSharedMemorySize, WE_SMEM_BYTES);

    // 1: weight prep  2: lin0 (fused agg/cnt zero)  3: k_we  4: k_msg (PROFILED)
    k_prep<<<(1024 * 128 + 255) / 256, 256>>>(mlp_w2, mlp_b2);
    k_lin0<<<(n * 32 + 255) / 256, 256>>>(x, lin0_w, lin0_b, n);
    k_we<<<(e + 127) / 128, 256, WE_SMEM_BYTES>>>(ea, mlp_w1, mlp_b1, e);
    k_msg<<<msg_grid, 256>>>(src, dst, e);

    // degree count (must precede first k_update; independent of k_msg)
    k_count<<<(e + 255) / 256, 256>>>(dst, e);
    k_update<<<(n * 32 + 1023) / 1024, 1024>>>(root_w, conv_b, gw_ih, gw_hh, gb_ih, gb_hh, n);

    for (int it = 1; it < 3; it++) {
        k_msg<<<msg_grid, 256>>>(src, dst, e);
        k_update<<<(n * 32 + 1023) / 1024, 1024>>>(root_w, conv_b, gw_ih, gw_hh, gb_ih, gb_hh, n);
    }

    k_final<<<(n * 32 + 255) / 256, 256>>>(lin1_w, lin1_b, lin2_w, lin2_b, (float*)d_out, n);
}

// round 17
// speedup vs baseline: 1.2445x; 1.2445x over previous
#include <cuda_runtime.h>
#include <cuda_fp16.h>
#include <cstdint>

// Problem constants
#define MAXN 100000
#define MAXE 200000

// -------- scratch (static device globals; no allocation) --------
// w_e stored fp16, TRANSPOSED per edge: g_weh[e][o][i] at flat col n = o*32+i
__device__ __half g_weh[(size_t)MAXE * 1024];   // 409.6 MB
__device__ __half g_w2h[1024 * 128];            // fp16 W2, rows PERMUTED by sr(n)
__device__ float g_b2p[1024];                   // permuted b2
__device__ float g_out[MAXN * 32];
__device__ float g_agg[MAXN * 32];
__device__ float g_cnt[MAXN];

__device__ __forceinline__ uint32_t smem_u32(const void* p) {
    uint32_t a;
    asm("{ .reg .u64 t; cvta.to.shared.u64 t, %1; cvt.u32.u64 %0, t; }" : "=r"(a) : "l"(p));
    return a;
}
__device__ __forceinline__ void ldsm_x4(uint32_t& r0, uint32_t& r1, uint32_t& r2, uint32_t& r3,
                                        uint32_t addr) {
    asm volatile("ldmatrix.sync.aligned.m8n8.x4.shared.b16 {%0,%1,%2,%3}, [%4];"
        : "=r"(r0), "=r"(r1), "=r"(r2), "=r"(r3) : "r"(addr));
}
__device__ __forceinline__ void mma16816(float* d, const uint32_t* a, const uint32_t* b) {
    asm volatile("mma.sync.aligned.m16n8k16.row.col.f32.f16.f16.f32 "
        "{%0,%1,%2,%3}, {%4,%5,%6,%7}, {%8,%9}, {%0,%1,%2,%3};"
        : "+f"(d[0]), "+f"(d[1]), "+f"(d[2]), "+f"(d[3])
        : "r"(a[0]), "r"(a[1]), "r"(a[2]), "r"(a[3]), "r"(b[0]), "r"(b[1]));
}
#define CP_ASYNC16(dst, src) \
    asm volatile("cp.async.cg.shared.global [%0], [%1], 16;" :: "r"(dst), "l"(src))
#define CP_COMMIT() asm volatile("cp.async.commit_group;")
#define CP_WAIT0()  asm volatile("cp.async.wait_group 0;")

// ============================================================
// prep: W2 fp32 [1024,128] -> fp16, rows permuted by sr(n); also permuted b2
// ============================================================
__global__ void k_prep(const float* __restrict__ w2, const float* __restrict__ b2) {
    int i = blockIdx.x * blockDim.x + threadIdx.x;
    if (i >= 1024 * 128) return;
    int n = i >> 7, k = i & 127;
    int sr = ((n & 31) << 5) | (n >> 5);
    g_w2h[n * 128 + k] = __float2half(w2[(size_t)sr * 128 + k]);
    if (k == 0) g_b2p[n] = b2[sr];
}

// ============================================================
// count / lin0 (lin0 fuses the agg+cnt zeroing)
// ============================================================
__global__ void k_count(const int* __restrict__ dst, int e) {
    int t = blockIdx.x * blockDim.x + threadIdx.x;
    if (t < e) atomicAdd(&g_cnt[dst[t]], 1.f);
}
__global__ void k_lin0(const float* __restrict__ x, const float* __restrict__ w,
                       const float* __restrict__ b, int n) {
    __shared__ float wT[16 * 32];
    __shared__ float bs[32];
    int t = threadIdx.x;
    for (int i = t; i < 512; i += blockDim.x) {
        int d = i >> 4, k = i & 15;
        wT[k * 32 + d] = w[i];
    }
    if (t < 32) bs[t] = b[t];
    __syncthreads();
    int warp = (blockIdx.x * blockDim.x + t) >> 5;
    int lane = t & 31;
    if (warp >= n) return;
    float xk = (lane < 16) ? x[(size_t)warp * 16 + lane] : 0.f;
    float acc = bs[lane];
#pragma unroll
    for (int k = 0; k < 16; k++) {
        float xv = __shfl_sync(0xffffffffu, xk, k);
        acc = fmaf(wT[k * 32 + lane], xv, acc);
    }
    size_t base = (size_t)warp * 32 + lane;
    g_out[base] = fmaxf(acc, 0.f);
    g_agg[base] = 0.f;          // fused init
    if (lane == 0) g_cnt[warp] = 0.f;
}

// ============================================================
// w_e GEMM via mma.sync: one CTA = 128 edges x FULL 1024 cols, K=128.
// ============================================================
#define STR_H 136
#define BUF_HALVES (128 * STR_H)
#define WE_SMEM_BYTES (3 * BUF_HALVES * 2)   // A + 2 B buffers

__global__ __launch_bounds__(256, 2) void k_we(
    const float* __restrict__ ea, const float* __restrict__ w1,
    const float* __restrict__ b1, int E)
{
    extern __shared__ __half smh[];
    __half* Asm = smh;                    // [128 el][136 k]
    __half* Bsm[2] = { smh + BUF_HALVES, smh + 2 * BUF_HALVES };
    __shared__ float eas[128 * 5];
    __shared__ float w1s[128 * 5];
    __shared__ float b1s[128];

    const int tid = threadIdx.x;
    const int w = tid >> 5;
    const int lane = tid & 31;
    const int ebase = blockIdx.x * 128;

#define STAGE_B(chunk, buf) do { \
        const __half* gsrc = g_w2h + (size_t)(chunk) * 128 * 128; \
        for (int i = tid; i < 2048; i += 256) { \
            int n = i >> 4, k0 = (i & 15) * 8; \
            uint32_t dsa = smem_u32(&Bsm[buf][n * STR_H + k0]); \
            CP_ASYNC16(dsa, gsrc + n * 128 + k0); \
        } \
        CP_COMMIT(); \
    } while (0)

    STAGE_B(0, 0);

    for (int i = tid; i < 640; i += 256) {
        int el = i / 5, j = i - el * 5;
        int ge = ebase + el;
        eas[i] = (ge < E) ? ea[(size_t)ge * 5 + j] : 0.f;
        w1s[i] = __ldg(&w1[i]);
    }
    if (tid < 128) b1s[tid] = __ldg(&b1[tid]);
    __syncthreads();

    for (int i = tid; i < 16384; i += 256) {
        int el = i >> 7, h = i & 127;
        float a = b1s[h];
        const float* e5 = &eas[el * 5];
        const float* w5 = &w1s[h * 5];
#pragma unroll
        for (int j = 0; j < 5; j++)
            a = fmaf(e5[j], w5[j], a);
        Asm[el * STR_H + h] = __float2half(fmaxf(a, 0.f));
    }
    CP_WAIT0();
    __syncthreads();

    const uint32_t Abase = smem_u32(Asm);
    const int R = (w & 3) * 32;
    const int C = (w >> 2) * 64;
    const int lt = lane >> 3;
    const int lr = lane & 7;
    const int qr = lane >> 2, qc = (lane & 3) * 2;

    for (int chunk = 0; chunk < 8; chunk++) {
        const int cur = chunk & 1;
        const uint32_t Bbase = smem_u32(Bsm[cur]);
        if (chunk < 7) STAGE_B(chunk + 1, cur ^ 1);

        float acc[2][8][4];
#pragma unroll
        for (int rt = 0; rt < 2; rt++)
#pragma unroll
            for (int nt = 0; nt < 8; nt++)
#pragma unroll
                for (int q = 0; q < 4; q++) acc[rt][nt][q] = 0.f;

#pragma unroll
        for (int ks = 0; ks < 8; ks++) {
            uint32_t a[2][4];
#pragma unroll
            for (int rt = 0; rt < 2; rt++) {
                int row = R + rt * 16 + (lt & 1) * 8 + lr;
                int kseg = lt >> 1;
                ldsm_x4(a[rt][0], a[rt][1], a[rt][2], a[rt][3],
                        Abase + (row * STR_H + ks * 16 + kseg * 8) * 2);
            }
            uint32_t b[8][2];
#pragma unroll
            for (int np = 0; np < 4; np++) {
                int n = C + np * 16 + (lt >> 1) * 8 + lr;
                int kseg = lt & 1;
                uint32_t r0, r1, r2, r3;
                ldsm_x4(r0, r1, r2, r3, Bbase + (n * STR_H + ks * 16 + kseg * 8) * 2);
                b[2 * np][0] = r0; b[2 * np][1] = r1;
                b[2 * np + 1][0] = r2; b[2 * np + 1][1] = r3;
            }
#pragma unroll
            for (int rt = 0; rt < 2; rt++)
#pragma unroll
                for (int nt = 0; nt < 8; nt++)
                    mma16816(acc[rt][nt], a[rt], b[nt]);
        }

        __syncthreads();
        {
            __half* Esm = Bsm[cur];
            const int colbase = chunk * 128;
#pragma unroll
            for (int rt = 0; rt < 2; rt++) {
#pragma unroll
                for (int h8 = 0; h8 < 2; h8++) {
                    int row = R + rt * 16 + h8 * 8 + qr;
#pragma unroll
                    for (int nt = 0; nt < 8; nt++) {
                        int c = C + nt * 8 + qc;
                        float d0 = acc[rt][nt][h8 * 2 + 0] + __ldg(&g_b2p[colbase + c]);
                        float d1 = acc[rt][nt][h8 * 2 + 1] + __ldg(&g_b2p[colbase + c + 1]);
                        *(__half2*)&Esm[row * STR_H + c] = __floats2half2_rn(d0, d1);
                    }
                }
            }
            __syncthreads();
            for (int i = tid; i < 2048; i += 256) {
                int row = i >> 4, seg = i & 15;
                int ge = ebase + row;
                if (ge < E)
                    *(uint4*)(g_weh + (size_t)ge * 1024 + colbase + seg * 8) =
                        *(const uint4*)&Esm[row * STR_H + seg * 8];
            }
        }
        if (chunk < 7) {
            CP_WAIT0();
            __syncthreads();
        }
    }
#undef STAGE_B
}

// ============================================================
// message pass: ONE edge per warp (reverted — 2-edge was not better)
// ============================================================
__global__ void k_msg(const int* __restrict__ src, const int* __restrict__ dst, int e) {
    int warp = (blockIdx.x * blockDim.x + threadIdx.x) >> 5;
    int lane = threadIdx.x & 31;
    if (warp >= e) return;
    int s = __ldg(&src[warp]);
    int d = __ldg(&dst[warp]);
    const uint4* wp = (const uint4*)(g_weh + (size_t)warp * 1024 + lane * 32);
    uint4 w0 = __ldcs(&wp[0]);
    uint4 w1 = __ldcs(&wp[1]);
    uint4 w2 = __ldcs(&wp[2]);
    uint4 w3 = __ldcs(&wp[3]);
    float sv = g_out[(size_t)s * 32 + lane];
    float acc = 0.f;
#define ACC2(u, i0) do { \
        float2 f_ = __half22float2(*(const __half2*)&(u)); \
        acc = fmaf(__shfl_sync(0xffffffffu, sv, (i0)), f_.x, acc); \
        acc = fmaf(__shfl_sync(0xffffffffu, sv, (i0) + 1), f_.y, acc); \
    } while (0)
    ACC2(w0.x, 0);  ACC2(w0.y, 2);  ACC2(w0.z, 4);  ACC2(w0.w, 6);
    ACC2(w1.x, 8);  ACC2(w1.y, 10); ACC2(w1.z, 12); ACC2(w1.w, 14);
    ACC2(w2.x, 16); ACC2(w2.y, 18); ACC2(w2.z, 20); ACC2(w2.w, 22);
    ACC2(w3.x, 24); ACC2(w3.y, 26); ACC2(w3.z, 28); ACC2(w3.w, 30);
#undef ACC2
    atomicAdd(&g_agg[(size_t)d * 32 + lane], acc);
}

// ============================================================
// fused NNConv-root + GRU update: FOUR nodes per warp.
// Weight-LDS amortized 4x -> MIO ops/node drop ~320 -> ~152.
// ============================================================
__global__ __launch_bounds__(512) void k_update(
    const float* __restrict__ root_w, const float* __restrict__ conv_b,
    const float* __restrict__ wih, const float* __restrict__ whh,
    const float* __restrict__ bih, const float* __restrict__ bhh, int n) {
    __shared__ float rootT[32 * 33];
    __shared__ float wihT[32 * 97];
    __shared__ float whhT[32 * 97];
    __shared__ float cb[32], bi[96], bh[96];
    int t = threadIdx.x;
    for (int i = t; i < 1024; i += blockDim.x) {
        int d = i >> 5, j = i & 31;
        rootT[j * 33 + d] = root_w[i];
    }
    for (int i = t; i < 3072; i += blockDim.x) {
        int rr = i >> 5, j = i & 31;
        wihT[j * 97 + rr] = wih[i];
        whhT[j * 97 + rr] = whh[i];
    }
    if (t < 32) cb[t] = conv_b[t];
    if (t < 96) { bi[t] = bih[t]; bh[t] = bhh[t]; }
    __syncthreads();

    int warp = (blockIdx.x * blockDim.x + t) >> 5;
    int lane = t & 31;
    int n0 = warp * 4;
    if (n0 >= n) return;

    float h[4], m[4];
    size_t base[4];
#pragma unroll
    for (int i = 0; i < 4; i++) {
        int node = (n0 + i < n) ? n0 + i : n0;
        base[i] = (size_t)node * 32 + lane;
        h[i] = g_out[base[i]];
        float c = fmaxf(g_cnt[node], 1.f);
        m[i] = g_agg[base[i]] / c + cb[lane];
        g_agg[base[i]] = 0.f;   // re-zero for next iteration
    }

    // root matvec, weight LDS shared by the 4 nodes
#pragma unroll
    for (int j = 0; j < 32; j++) {
        float rw = rootT[j * 33 + lane];
#pragma unroll
        for (int i = 0; i < 4; i++)
            m[i] = fmaf(rw, __shfl_sync(0xffffffffu, h[i], j), m[i]);
    }
#pragma unroll
    for (int i = 0; i < 4; i++) m[i] = fmaxf(m[i], 0.f);

    float gr[4], gz[4], gn[4], hr[4], hz[4], hn[4];
#pragma unroll
    for (int i = 0; i < 4; i++) {
        gr[i] = bi[lane]; gz[i] = bi[32 + lane]; gn[i] = bi[64 + lane];
        hr[i] = bh[lane]; hz[i] = bh[32 + lane]; hn[i] = bh[64 + lane];
    }
#pragma unroll
    for (int j = 0; j < 32; j++) {
        float w0 = wihT[j * 97 + lane];
        float w1 = wihT[j * 97 + 32 + lane];
        float w2 = wihT[j * 97 + 64 + lane];
        float v0 = whhT[j * 97 + lane];
        float v1 = whhT[j * 97 + 32 + lane];
        float v2 = whhT[j * 97 + 64 + lane];
#pragma unroll
        for (int i = 0; i < 4; i++) {
            float mj = __shfl_sync(0xffffffffu, m[i], j);
            float hj = __shfl_sync(0xffffffffu, h[i], j);
            gr[i] = fmaf(w0, mj, gr[i]);
            gz[i] = fmaf(w1, mj, gz[i]);
            gn[i] = fmaf(w2, mj, gn[i]);
            hr[i] = fmaf(v0, hj, hr[i]);
            hz[i] = fmaf(v1, hj, hz[i]);
            hn[i] = fmaf(v2, hj, hn[i]);
        }
    }
#pragma unroll
    for (int i = 0; i < 4; i++) {
        if (n0 + i >= n) break;
        float r = 1.f / (1.f + __expf(-(gr[i] + hr[i])));
        float z = 1.f / (1.f + __expf(-(gz[i] + hz[i])));
        float nn = tanhf(gn[i] + r * hn[i]);
        g_out[base[i]] = (1.f - z) * nn + z * h[i];
    }
}

// ============================================================
// final readout
// ============================================================
__global__ void k_final(const float* __restrict__ l1w, const float* __restrict__ l1b,
                        const float* __restrict__ l2w, const float* __restrict__ l2b,
                        float* __restrict__ out, int n) {
    __shared__ float w1T[32 * 33];
    __shared__ float b1s[32], w2s[32];
    int t = threadIdx.x;
    for (int i = t; i < 1024; i += blockDim.x) {
        int d = i >> 5, j = i & 31;
        w1T[j * 33 + d] = l1w[i];
    }
    if (t < 32) { b1s[t] = l1b[t]; w2s[t] = l2w[t]; }
    __syncthreads();

    int warp = (blockIdx.x * blockDim.x + t) >> 5;
    int lane = t & 31;
    if (warp >= n) return;
    float h = g_out[(size_t)warp * 32 + lane];
    float acc = b1s[lane];
#pragma unroll
    for (int j = 0; j < 32; j++) {
        float hj = __shfl_sync(0xffffffffu, h, j);
        acc = fmaf(w1T[j * 33 + lane], hj, acc);
    }
    acc = fmaxf(acc, 0.f);
    float p = acc * w2s[lane];
#pragma unroll
    for (int off = 16; off; off >>= 1) p += __shfl_xor_sync(0xffffffffu, p, off);
    if (lane == 0) out[warp] = p + __ldg(&l2b[0]);
}

// ============================================================
// launcher — k_msg (1-edge) is the 4th launch (profiled slot)
// ============================================================
extern "C" void kernel_launch(void* const* d_in, const int* in_sizes, int n_in,
                              void* d_out, int out_size) {
    const float* x      = (const float*)d_in[0];
    const int*   ei     = (const int*)  d_in[1];
    const float* ea     = (const float*)d_in[2];
    const float* lin0_w = (const float*)d_in[3];
    const float* lin0_b = (const float*)d_in[4];
    const float* mlp_w1 = (const float*)d_in[5];
    const float* mlp_b1 = (const float*)d_in[6];
    const float* mlp_w2 = (const float*)d_in[7];
    const float* mlp_b2 = (const float*)d_in[8];
    const float* root_w = (const float*)d_in[9];
    const float* conv_b = (const float*)d_in[10];
    const float* gw_ih  = (const float*)d_in[11];
    const float* gw_hh  = (const float*)d_in[12];
    const float* gb_ih  = (const float*)d_in[13];
    const float* gb_hh  = (const float*)d_in[14];
    const float* lin1_w = (const float*)d_in[15];
    const float* lin1_b = (const float*)d_in[16];
    const float* lin2_w = (const float*)d_in[17];
    const float* lin2_b = (const float*)d_in[18];

    const int n = in_sizes[0] / 16;   // 100000
    const int e = in_sizes[2] / 5;    // 200000
    const int* src = ei;
    const int* dst = ei + e;
    const int upd_grid = (n + 63) / 64;   // 512 threads = 16 warps x 4 nodes

    cudaFuncSetAttribute(k_we, cudaFuncAttributeMaxDynamicSharedMemorySize, WE_SMEM_BYTES);

    // 1: weight prep  2: lin0 (fused agg/cnt zero)  3: k_we  4: k_msg (PROFILED)
    k_prep<<<(1024 * 128 + 255) / 256, 256>>>(mlp_w2, mlp_b2);
    k_lin0<<<(n * 32 + 255) / 256, 256>>>(x, lin0_w, lin0_b, n);
    k_we<<<(e + 127) / 128, 256, WE_SMEM_BYTES>>>(ea, mlp_w1, mlp_b1, e);
    k_msg<<<(e * 32 + 255) / 256, 256>>>(src, dst, e);

    // degree count (must precede first k_update; independent of k_msg)
    k_count<<<(e + 255) / 256, 256>>>(dst, e);
    k_update<<<upd_grid, 512>>>(root_w, conv_b, gw_ih, gw_hh, gb_ih, gb_hh, n);

    for (int it = 1; it < 3; it++) {
        k_msg<<<(e * 32 + 255) / 256, 256>>>(src, dst, e);
        k_update<<<upd_grid, 512>>>(root_w, conv_b, gw_ih, gw_hh, gb_ih, gb_hh, n);
    }

    k_final<<<(n * 32 + 255) / 256, 256>>>(lin1_w, lin1_b, lin2_w, lin2_b, (float*)d_out, n);
}